// round 1
// baseline (speedup 1.0000x reference)
#include <cuda_runtime.h>

#define NB 16
#define L  1024
#define S  512
#define KW 3
#define KKTOT 1536

#define BM 128
#define BN 128
#define BK 16
#define TM 8
#define TN 8

// scratch (no runtime allocation allowed)
__device__ float g_M[(size_t)NB * L * S];      // 32 MB
__device__ float g_qbias[NB * L];
__device__ float g_rbias[NB * L];

// ---------------------------------------------------------------------------
// Kernel 1: per-row biases.
// qbias[b,i] = dot(q[b,i,:], Wb) + bb
// rbias[b,j] = sum_t dot(bk[:,t], k[b,j+t-1,:]) + bias_b
// ---------------------------------------------------------------------------
__global__ void bias_kernel(const float* __restrict__ q, const float* __restrict__ k,
                            const float* __restrict__ bk, const float* __restrict__ Wb,
                            const float* __restrict__ bb, const float* __restrict__ bias_b) {
    int row  = blockIdx.x * (blockDim.x >> 5) + (threadIdx.x >> 5);
    int lane = threadIdx.x & 31;
    if (row >= NB * L) return;
    int b = row / L, j = row % L;
    const float* qrow = q + (size_t)row * S;
    float accq = 0.f, accr = 0.f;
    for (int c = lane; c < S; c += 32) {
        accq += qrow[c] * Wb[c];
        #pragma unroll
        for (int t = 0; t < KW; t++) {
            int jj = j + t - 1;
            if (jj >= 0 && jj < L)
                accr += bk[c * KW + t] * k[((size_t)b * L + jj) * S + c];
        }
    }
    #pragma unroll
    for (int o = 16; o > 0; o >>= 1) {
        accq += __shfl_xor_sync(0xffffffffu, accq, o);
        accr += __shfl_xor_sync(0xffffffffu, accr, o);
    }
    if (lane == 0) {
        g_qbias[row] = accq + bb[0];
        g_rbias[row] = accr + bias_b[0];
    }
}

// ---------------------------------------------------------------------------
// Kernel 2: M[b,j,qd] = sum_{kk} Kwin[b, j, kk] * Wkr[kk, qd]
//   kk = t*S + c ;  Kwin[b,j,kk] = k[b, j+t-1, c] (0 outside) ;
//   Wkr[kk, qd] = Wk[c*KW + t, qd]
// Implicit-window SGEMM, M-dim = j (1024), N = qd (512), K = 1536, per batch.
// ---------------------------------------------------------------------------
__global__ __launch_bounds__(256, 2)
void mgemm_kernel(const float* __restrict__ kten, const float* __restrict__ Wk) {
    __shared__ float As[BK][BM + 4];
    __shared__ float Bs[BK][BN + 4];

    int b  = blockIdx.z;
    int n0 = blockIdx.x * BN;   // qd tile
    int m0 = blockIdx.y * BM;   // j tile
    int tid = threadIdx.x;
    int tm = (tid >> 4) * TM;   // 16 row groups
    int tn = (tid & 15) * TN;   // 16 col groups

    const float* kb = kten + (size_t)b * L * S;
    float acc[TM][TN] = {};

    for (int kk0 = 0; kk0 < KKTOT; kk0 += BK) {
        int t  = kk0 / S;       // constant within a BK=16 chunk (512 % 16 == 0)
        int c0 = kk0 % S;

        // A tile: 128 rows x 16 K, 2 float4 per thread, transposed store
        #pragma unroll
        for (int s = 0; s < 2; s++) {
            int idx = tid + 256 * s;
            int r   = idx >> 2;          // 0..127 (j within tile)
            int kc  = (idx & 3) * 4;     // 0,4,8,12
            int jj  = m0 + r + t - 1;
            float4 v = make_float4(0.f, 0.f, 0.f, 0.f);
            if (jj >= 0 && jj < L)
                v = *reinterpret_cast<const float4*>(kb + (size_t)jj * S + c0 + kc);
            As[kc + 0][r] = v.x; As[kc + 1][r] = v.y;
            As[kc + 2][r] = v.z; As[kc + 3][r] = v.w;
        }
        // B tile: 16 K-rows x 128 cols, 2 float4 per thread, direct store
        #pragma unroll
        for (int s = 0; s < 2; s++) {
            int idx = tid + 256 * s;
            int r   = idx >> 5;          // 0..15 (kc)
            int nc  = (idx & 31) * 4;    // 0..124
            int rW  = (c0 + r) * KW + t;
            float4 v = *reinterpret_cast<const float4*>(Wk + (size_t)rW * S + n0 + nc);
            *reinterpret_cast<float4*>(&Bs[r][nc]) = v;
        }
        __syncthreads();

        #pragma unroll
        for (int kc = 0; kc < BK; kc++) {
            float a[TM], bb2[TN];
            #pragma unroll
            for (int i = 0; i < TM; i++) a[i] = As[kc][tm + i];
            #pragma unroll
            for (int jx = 0; jx < TN; jx++) bb2[jx] = Bs[kc][tn + jx];
            #pragma unroll
            for (int i = 0; i < TM; i++)
                #pragma unroll
                for (int jx = 0; jx < TN; jx++)
                    acc[i][jx] += a[i] * bb2[jx];
        }
        __syncthreads();
    }

    float* Mb = g_M + (size_t)b * L * S;
    #pragma unroll
    for (int i = 0; i < TM; i++) {
        #pragma unroll
        for (int jx = 0; jx < TN; jx += 4) {
            float4 v = make_float4(acc[i][jx], acc[i][jx + 1], acc[i][jx + 2], acc[i][jx + 3]);
            *reinterpret_cast<float4*>(Mb + (size_t)(m0 + tm + i) * S + n0 + tn + jx) = v;
        }
    }
}

// ---------------------------------------------------------------------------
// Kernel 3: scores[b,i,j] = sum_k q[b,i,k] * M[b,j,k] + qbias[b,i] + rbias[b,j]
// Batched NT SGEMM: M=1024(i), N=1024(j), K=512, per batch.
// ---------------------------------------------------------------------------
__global__ __launch_bounds__(256, 2)
void score_kernel(const float* __restrict__ q, float* __restrict__ out) {
    __shared__ float As[BK][BM + 4];
    __shared__ float Bs[BK][BN + 4];

    int b  = blockIdx.z;
    int n0 = blockIdx.x * BN;   // j tile
    int m0 = blockIdx.y * BM;   // i tile
    int tid = threadIdx.x;
    int tm = (tid >> 4) * TM;
    int tn = (tid & 15) * TN;

    const float* qa = q   + ((size_t)b * L + m0) * S;
    const float* Mb = g_M + ((size_t)b * L + n0) * S;
    float acc[TM][TN] = {};

    for (int k0 = 0; k0 < S; k0 += BK) {
        #pragma unroll
        for (int s = 0; s < 2; s++) {
            int idx = tid + 256 * s;
            int r   = idx >> 2;
            int kc  = (idx & 3) * 4;
            float4 v = *reinterpret_cast<const float4*>(qa + (size_t)r * S + k0 + kc);
            As[kc + 0][r] = v.x; As[kc + 1][r] = v.y;
            As[kc + 2][r] = v.z; As[kc + 3][r] = v.w;
        }
        #pragma unroll
        for (int s = 0; s < 2; s++) {
            int idx = tid + 256 * s;
            int r   = idx >> 2;
            int kc  = (idx & 3) * 4;
            float4 v = *reinterpret_cast<const float4*>(Mb + (size_t)r * S + k0 + kc);
            Bs[kc + 0][r] = v.x; Bs[kc + 1][r] = v.y;
            Bs[kc + 2][r] = v.z; Bs[kc + 3][r] = v.w;
        }
        __syncthreads();

        #pragma unroll
        for (int kc = 0; kc < BK; kc++) {
            float a[TM], bb2[TN];
            #pragma unroll
            for (int i = 0; i < TM; i++) a[i] = As[kc][tm + i];
            #pragma unroll
            for (int jx = 0; jx < TN; jx++) bb2[jx] = Bs[kc][tn + jx];
            #pragma unroll
            for (int i = 0; i < TM; i++)
                #pragma unroll
                for (int jx = 0; jx < TN; jx++)
                    acc[i][jx] += a[i] * bb2[jx];
        }
        __syncthreads();
    }

    float rb[TN];
    #pragma unroll
    for (int jx = 0; jx < TN; jx++) rb[jx] = g_rbias[b * L + n0 + tn + jx];

    #pragma unroll
    for (int i = 0; i < TM; i++) {
        float qb = g_qbias[b * L + m0 + tm + i];
        float* orow = out + ((size_t)b * L + (m0 + tm + i)) * L + n0 + tn;
        #pragma unroll
        for (int jx = 0; jx < TN; jx += 4) {
            float4 v = make_float4(acc[i][jx + 0] + qb + rb[jx + 0],
                                   acc[i][jx + 1] + qb + rb[jx + 1],
                                   acc[i][jx + 2] + qb + rb[jx + 2],
                                   acc[i][jx + 3] + qb + rb[jx + 3]);
            *reinterpret_cast<float4*>(orow + jx) = v;
        }
    }
}

// ---------------------------------------------------------------------------
extern "C" void kernel_launch(void* const* d_in, const int* in_sizes, int n_in,
                              void* d_out, int out_size) {
    const float* q      = (const float*)d_in[0];
    const float* k      = (const float*)d_in[1];
    const float* Wk     = (const float*)d_in[2];
    const float* bk     = (const float*)d_in[3];
    const float* Wb     = (const float*)d_in[4];
    const float* bb     = (const float*)d_in[5];
    const float* bias_b = (const float*)d_in[6];
    float* out = (float*)d_out;

    // biases: one warp per (b, row)
    bias_kernel<<<(NB * L) / 8, 256>>>(q, k, bk, Wb, bb, bias_b);

    // M = implicit-window GEMM
    dim3 g2(S / BN, L / BM, NB);
    mgemm_kernel<<<g2, 256>>>(k, Wk);

    // scores = batched NT GEMM + bias epilogue
    dim3 g3(L / BN, L / BM, NB);
    score_kernel<<<g3, 256>>>(q, out);
}